// round 1
// baseline (speedup 1.0000x reference)
#include <cuda_runtime.h>
#include <cstdint>
#include <cstddef>

#define Dm   512
#define Bm_  16
#define Sm   4096
#define G3   1536
#define NBLK 128
#define NTHR 256

// Scratch (device globals: allocation-free per harness rules)
__device__ float g_gi[(size_t)Bm_ * Sm * G3];   // [b][t][1536]  (384 MB)
__device__ float g_rnn[(size_t)Bm_ * Sm * Dm];  // [b][t][512]   (128 MB)
__device__ float g_h[2][Dm * Bm_];              // ping-pong H, [k][b] layout
__device__ unsigned g_cnt;                      // grid barrier counter

__global__ void init_state()
{
    int tid = blockIdx.x * blockDim.x + threadIdx.x;
    if (tid == 0) g_cnt = 0u;
    if (tid < Dm * Bm_) g_h[0][tid] = 0.f;
}

// ---------------------------------------------------------------------------
// SGEMM: C[M,N] = A[M,K] @ B[K,N] + bias[N]
// BM=128, BN=64, BK=16, 256 threads, 8x4 per-thread tile
// ---------------------------------------------------------------------------
__global__ void __launch_bounds__(256) sgemm_bias(
    const float* __restrict__ A, const float* __restrict__ Bmat,
    const float* __restrict__ bias, float* __restrict__ C,
    int M, int N, int K)
{
    __shared__ float As[16][132];   // transposed A tile, padded (conflict-free reads)
    __shared__ float Bs[16][64];

    const int tid = threadIdx.x;
    const int tx = tid & 15;        // n-group (4 cols)
    const int ty = tid >> 4;        // m-group (8 rows)
    const int m0 = blockIdx.y * 128;
    const int n0 = blockIdx.x * 64;

    const int a_row = tid >> 2;          // 0..63
    const int a_kq  = (tid & 3) * 4;     // 0,4,8,12

    float acc[8][4];
#pragma unroll
    for (int i = 0; i < 8; ++i)
#pragma unroll
        for (int j = 0; j < 4; ++j) acc[i][j] = 0.f;

    for (int k0 = 0; k0 < K; k0 += 16) {
#pragma unroll
        for (int j = 0; j < 2; ++j) {
            int row = a_row + j * 64;
            float4 v = *(const float4*)(A + (size_t)(m0 + row) * K + k0 + a_kq);
            As[a_kq + 0][row] = v.x;
            As[a_kq + 1][row] = v.y;
            As[a_kq + 2][row] = v.z;
            As[a_kq + 3][row] = v.w;
        }
        {
            float4 v = *(const float4*)(Bmat + (size_t)(k0 + ty) * N + n0 + tx * 4);
            *(float4*)&Bs[ty][tx * 4] = v;
        }
        __syncthreads();

#pragma unroll
        for (int kk = 0; kk < 16; ++kk) {
            float a[8], b[4];
            *(float4*)&a[0] = *(const float4*)&As[kk][ty * 8];
            *(float4*)&a[4] = *(const float4*)&As[kk][ty * 8 + 4];
            *(float4*)&b[0] = *(const float4*)&Bs[kk][tx * 4];
#pragma unroll
            for (int i = 0; i < 8; ++i)
#pragma unroll
                for (int j = 0; j < 4; ++j)
                    acc[i][j] += a[i] * b[j];
        }
        __syncthreads();
    }

    float4 bv = *(const float4*)(bias + n0 + tx * 4);
#pragma unroll
    for (int i = 0; i < 8; ++i) {
        float4 o;
        o.x = acc[i][0] + bv.x;
        o.y = acc[i][1] + bv.y;
        o.z = acc[i][2] + bv.z;
        o.w = acc[i][3] + bv.w;
        *(float4*)(C + (size_t)(m0 + ty * 8 + i) * N + n0 + tx * 4) = o;
    }
}

// ---------------------------------------------------------------------------
// Persistent GRU scan. 128 blocks, each owns 4 h-dims (12 Wh columns resident
// in SMEM for all 4096 steps). Per step: reload H (32KB, [k][b]) from L2,
// 8 warps split K (64 each), lanes split (16 batches x 2 column-halves),
// smem tree-reduce, 64 threads do gates, global grid barrier.
// ---------------------------------------------------------------------------
extern __shared__ float smem_dyn[];

__global__ void __launch_bounds__(NTHR, 1) gru_scan(
    const float* __restrict__ Wh, const float* __restrict__ bhn)
{
    float* wh_s = smem_dyn;                 // [512][12]
    float* h_s  = smem_dyn + Dm * 12;       // [512][16]
    float* red  = h_s + Dm * 16;            // [8][192]

    const int tid = threadIdx.x;
    const int d0  = blockIdx.x * 4;

    // Load Wh column slice once (cols: r{d0..d0+3}, z{...}, n{...})
    for (int i = tid; i < Dm * 3; i += NTHR) {
        int k = i / 3, g = i - k * 3;
        float4 v = *(const float4*)(Wh + (size_t)k * G3 + g * Dm + d0);
        *(float4*)&wh_s[k * 12 + g * 4] = v;
    }

    const int warp = tid >> 5, lane = tid & 31;
    const int b  = lane & 15;
    const int c0 = (lane >> 4) * 6;     // 0 or 6
    const int k0 = warp * 64;
    const int gd = tid >> 4, gb = tid & 15;   // gate-thread mapping (tid<64)
    float my_bhn = 0.f;
    if (tid < 64) my_bhn = bhn[d0 + gd];

    unsigned target = 0;
    for (int t = 0; t < Sm; ++t) {
        const float* Hc = g_h[t & 1];
        float* Hn = g_h[(t & 1) ^ 1];

        // prefetch input-side gates for this step (latency hidden by k-loop)
        float gir = 0.f, giz = 0.f, gin = 0.f;
        if (tid < 64) {
            const float* gp = g_gi + ((size_t)gb * Sm + t) * G3 + d0 + gd;
            gir = __ldg(gp);
            giz = __ldg(gp + Dm);
            gin = __ldg(gp + 2 * Dm);
        }

        // load H state (coalesced, [k][b] layout, no transpose)
#pragma unroll
        for (int i = 0; i < 8; ++i) {
            int idx = (tid + i * NTHR) << 2;
            *(float4*)&h_s[idx] = *(const float4*)&Hc[idx];
        }
        __syncthreads();

        // partial dot products: 6 columns x 1 batch per lane over 64 k
        float a0 = 0.f, a1 = 0.f, a2 = 0.f, a3 = 0.f, a4 = 0.f, a5 = 0.f;
#pragma unroll 4
        for (int k = k0; k < k0 + 64; ++k) {
            float hv = h_s[k * 16 + b];
            float2 w01 = *(const float2*)&wh_s[k * 12 + c0];
            float2 w23 = *(const float2*)&wh_s[k * 12 + c0 + 2];
            float2 w45 = *(const float2*)&wh_s[k * 12 + c0 + 4];
            a0 += w01.x * hv; a1 += w01.y * hv;
            a2 += w23.x * hv; a3 += w23.y * hv;
            a4 += w45.x * hv; a5 += w45.y * hv;
        }
        {
            float* rw = red + warp * 192 + b;
            rw[(c0 + 0) * 16] = a0;
            rw[(c0 + 1) * 16] = a1;
            rw[(c0 + 2) * 16] = a2;
            rw[(c0 + 3) * 16] = a3;
            rw[(c0 + 4) * 16] = a4;
            rw[(c0 + 5) * 16] = a5;
        }
        __syncthreads();

        if (tid < 64) {
            float ghr = 0.f, ghz = 0.f, ghn = 0.f;
#pragma unroll
            for (int w = 0; w < 8; ++w) {
                const float* rp = red + w * 192 + gb;
                ghr += rp[(0 + gd) * 16];
                ghz += rp[(4 + gd) * 16];
                ghn += rp[(8 + gd) * 16];
            }
            float r = 1.f / (1.f + __expf(-(gir + ghr)));
            float z = 1.f / (1.f + __expf(-(giz + ghz)));
            float n = tanhf(gin + r * (ghn + my_bhn));
            float hold = h_s[(d0 + gd) * 16 + gb];
            float hnew = (1.f - z) * n + z * hold;
            Hn[(d0 + gd) * 16 + gb] = hnew;
            g_rnn[((size_t)gb * Sm + t) * Dm + d0 + gd] = hnew;
        }
        __syncthreads();

        // global grid barrier (monotone counter, no reset within launch)
        target += NBLK;
        if (tid == 0) {
            __threadfence();
            atomicAdd(&g_cnt, 1u);
            unsigned v;
            do {
                asm volatile("ld.acquire.gpu.u32 %0, [%1];" : "=r"(v) : "l"(&g_cnt));
            } while (v < target);
        }
        __syncthreads();
    }
}

// ---------------------------------------------------------------------------
extern "C" void kernel_launch(void* const* d_in, const int* in_sizes, int n_in,
                              void* d_out, int out_size)
{
    const float* x   = (const float*)d_in[0];
    const float* Wi  = (const float*)d_in[1];
    const float* bi  = (const float*)d_in[2];
    const float* Wh  = (const float*)d_in[3];
    const float* bhn = (const float*)d_in[4];
    const float* Wo  = (const float*)d_in[5];
    const float* bo  = (const float*)d_in[6];
    float* out = (float*)d_out;

    void* gi_ptr = nullptr;
    void* rnn_ptr = nullptr;
    cudaGetSymbolAddress(&gi_ptr, g_gi);
    cudaGetSymbolAddress(&rnn_ptr, g_rnn);

    const int smem_bytes = (Dm * 12 + Dm * 16 + 8 * 192) * (int)sizeof(float); // 63488
    cudaFuncSetAttribute(gru_scan, cudaFuncAttributeMaxDynamicSharedMemorySize, smem_bytes);

    init_state<<<32, 256>>>();

    dim3 g1(G3 / 64, (Bm_ * Sm) / 128);
    sgemm_bias<<<g1, 256>>>(x, Wi, bi, (float*)gi_ptr, Bm_ * Sm, G3, Dm);

    gru_scan<<<NBLK, NTHR, smem_bytes>>>(Wh, bhn);

    dim3 g2(Dm / 64, (Bm_ * Sm) / 128);
    sgemm_bias<<<g2, 256>>>((const float*)rnn_ptr, Wo, bo, out, Bm_ * Sm, Dm, Dm);
}